// round 9
// baseline (speedup 1.0000x reference)
#include <cuda_runtime.h>

// HausdorffDTLoss: B=4, C=2, H=W=256, ALPHA=2 — matches the reference 2-pass
// brute-force squared EDT exactly (up to final-sum association):
//  - row pass stores packed u16 nearest-opposite-bit distances (fg low16,
//    bg high16; the half not matching the pixel's own bit is exactly 0;
//    sentinel d=1024 when the row has no opposite bit, 1024^2 = 2^20).
//  - column pass: exact integer min of d*d + r^2 (finite < 2^18, fp32-exact
//    ints in the reference too; sentinel sums >= 2^20 only win when every row
//    is sentinel, reproducing the reference's exact 1e9). Branchless window
//    r<=4 is exact when best <= 25; rare lanes do an exact global column scan.
// 256 blocks per kernel (well under one wave); colpass launched with PDL so
// its launch overlaps the row pass (griddepsync before reading g_pack).

#define HH 256
#define WW 256
#define BB 4
#define SENT 1024u
#define SENTP 0x04000400u

__device__ uint2 g_pack[BB][HH * WW];

// ---------------------------------------------------------------------------
// nearest opposite-valued bit in a 256-bit row mask
// ---------------------------------------------------------------------------
__device__ __forceinline__ int nearest_opp(const unsigned* __restrict__ w, int i,
                                           unsigned inv) {
    const int k = i >> 5, bpos = i & 31;
    unsigned m = (w[k] ^ inv) & (0xFFFFFFFFu >> (31 - bpos));
    int L = -1000000, kk = k;
    while (true) {
        if (m) { L = (kk << 5) + 31 - __clz(m); break; }
        if (--kk < 0) break;
        m = w[kk] ^ inv;
    }
    m = (w[k] ^ inv) & (0xFFFFFFFFu << bpos);
    int R = 1000000;
    kk = k;
    while (true) {
        if (m) { R = (kk << 5) + __ffs(m) - 1; break; }
        if (++kk > 7) break;
        m = w[kk] ^ inv;
    }
    return min(i - L, R - i);
}

// ---------------------------------------------------------------------------
// K1: row pass, 4 rows per block. grid=(64, 4), block=256. Also zeroes out.
// ---------------------------------------------------------------------------
__global__ __launch_bounds__(256) void k_rowpass(const float* __restrict__ mo,
                                                 const float* __restrict__ gt,
                                                 float* __restrict__ out) {
    const int rq = blockIdx.x;  // row quad
    const int b = blockIdx.y;
    const int t = threadIdx.x;

    __shared__ unsigned P[4][8], G[4][8];
    float m0[4], m1[4], gv[4];
    bool pb[4], gb[4];

#pragma unroll
    for (int k = 0; k < 4; ++k) {  // 12 independent LDGs in flight
        int r = rq * 4 + k;
        m0[k] = mo[((b * 2 + 0) * HH + r) * WW + t];
        m1[k] = mo[((b * 2 + 1) * HH + r) * WW + t];
        gv[k] = gt[(b * HH + r) * WW + t];
    }
#pragma unroll
    for (int k = 0; k < 4; ++k) {
        pb[k] = (m1[k] > m0[k]);  // argmax ties -> channel 0
        gb[k] = (gv[k] > 0.5f);
        unsigned bp = __ballot_sync(0xFFFFFFFFu, pb[k]);
        unsigned bg = __ballot_sync(0xFFFFFFFFu, gb[k]);
        if ((t & 31) == 0) {
            P[k][t >> 5] = bp;
            G[k][t >> 5] = bg;
        }
    }
    __syncthreads();

#pragma unroll
    for (int k = 0; k < 4; ++k) {
        int r = rq * 4 + k;
        int pd = nearest_opp(P[k], t, pb[k] ? 0xFFFFFFFFu : 0u);
        int gd = nearest_opp(G[k], t, gb[k] ? 0xFFFFFFFFu : 0u);
        unsigned ps = (pd > 255) ? SENT : (unsigned)pd;
        unsigned gs = (gd > 255) ? SENT : (unsigned)gd;
        uint2 o;
        o.x = pb[k] ? ps : (ps << 16);  // fg dist low16, bg dist high16
        o.y = gb[k] ? gs : (gs << 16);
        g_pack[b][r * WW + t] = o;
    }

    if (rq == 0 && b == 0 && t == 0) out[0] = 0.0f;
}

// ---------------------------------------------------------------------------
// rare exact extension beyond the r<=4 window (global column scan)
// ---------------------------------------------------------------------------
__device__ __noinline__ unsigned extend(const uint2* __restrict__ src, int i,
                                        int col, int sh, int useY,
                                        unsigned best) {
#pragma unroll 1
    for (int r = 5; r < 256; ++r) {
        unsigned rr = (unsigned)(r * r);
        if (rr >= best) break;
        int lo = i - r, hi = i + r;
        if (lo >= 0) {
            uint2 w = __ldg(&src[lo * WW + col]);
            unsigned d = ((useY ? w.y : w.x) >> sh) & 0xFFFFu;
            best = min(best, d * d + rr);
        }
        if (hi < 256) {
            uint2 w = __ldg(&src[hi * WW + col]);
            unsigned d = ((useY ? w.y : w.x) >> sh) & 0xFFFFu;
            best = min(best, d * d + rr);
        }
    }
    return best;
}

// ---------------------------------------------------------------------------
// per-pixel loss term from the column tile (tile stride 32 uint2)
// ---------------------------------------------------------------------------
__device__ __forceinline__ float pixel_term(const uint2* __restrict__ tcol,
                                            int ti, const uint2* __restrict__ src,
                                            int i, int col) {
    uint2 v = tcol[ti * 32];
    bool pbit = (v.x & 0xFFFFu) != 0u;  // own-plane dist >= 1 iff bit set
    bool gbit = (v.y & 0xFFFFu) != 0u;
    int shp = pbit ? 0 : 16;
    int shg = gbit ? 0 : 16;

    unsigned bestP = 0xFFFFFFFFu, bestG = 0xFFFFFFFFu;
#pragma unroll
    for (int dr = -4; dr <= 4; ++dr) {
        uint2 w = tcol[(ti + dr) * 32];
        unsigned rr = (unsigned)(dr * dr);
        unsigned dp = (w.x >> shp) & 0xFFFFu;
        unsigned dg = (w.y >> shg) & 0xFFFFu;
        bestP = min(bestP, dp * dp + rr);
        bestG = min(bestG, dg * dg + rr);
    }
    if (bestP > 25u) bestP = extend(src, i, col, shp, 0, bestP);
    if (bestG > 25u) bestG = extend(src, i, col, shg, 1, bestG);

    float e = (pbit != gbit) ? 1.0f : 0.0f;
    float Dp = (bestP >= (1u << 20)) ? 1.0e9f : (float)bestP;
    float sp = sqrtf(Dp);
    float pterm = sp * sp;  // fl(sqrt(D)^2): matches reference rounding
    if (!pbit && bestP >= (1u << 20)) pterm = 0.0f;  // fg-empty guard
    float Dg = (bestG >= (1u << 20)) ? 1.0e9f : (float)bestG;
    float sg = sqrtf(Dg);
    float gterm = sg * sg;
    if (!gbit && bestG >= (1u << 20)) gterm = 0.0f;
    return e * (pterm + gterm);
}

// ---------------------------------------------------------------------------
// K2: column pass + fused loss. grid=(8 colgroups, 8 rowtiles, 4 batches)
// = 256 blocks, block=256, 32x32 output tile (4 px/thread), 40x32 smem tile.
// ---------------------------------------------------------------------------
__global__ __launch_bounds__(256) void k_colpass(float* __restrict__ out) {
    const int cg = blockIdx.x;  // 32-col group
    const int ry = blockIdx.y;
    const int b = blockIdx.z;
    const int t = threadIdx.x;
    const int base = ry * 32 - 4;

    __shared__ uint2 tile[40 * 32];  // 10 KB
    __shared__ float wsum[8];

#if __CUDA_ARCH__ >= 900
    cudaGridDependencySynchronize();  // PDL: wait for k_rowpass's writes
#endif

    const uint2* src = g_pack[b];
#pragma unroll
    for (int k = 0; k < 5; ++k) {  // 5 independent LDGs in flight
        int idx = t + k * 256;
        int grow = base + (idx >> 5), c2 = idx & 31;
        tile[idx] = ((unsigned)grow < 256u) ? src[grow * WW + cg * 32 + c2]
                                            : make_uint2(SENTP, SENTP);
    }
    __syncthreads();

    const int c = t & 31;
    const int rb = t >> 5;  // 0..7
    const int col = cg * 32 + c;
    const uint2* tcol = tile + c;

    float acc = 0.0f;
#pragma unroll
    for (int k = 0; k < 4; ++k) {
        int row = rb + k * 8;
        acc += pixel_term(tcol, row + 4, src, ry * 32 + row, col);
    }

    // deterministic block reduction, then one REDG add of the scaled partial
#pragma unroll
    for (int o = 16; o > 0; o >>= 1) acc += __shfl_down_sync(0xFFFFFFFFu, acc, o);
    if ((t & 31) == 0) wsum[t >> 5] = acc;
    __syncthreads();
    if (t == 0) {
        float s = 0.0f;
#pragma unroll
        for (int j = 0; j < 8; ++j) s += wsum[j];
        atomicAdd(out, s * (1.0f / 262144.0f));
    }
}

extern "C" void kernel_launch(void* const* d_in, const int* in_sizes, int n_in,
                              void* d_out, int out_size) {
    const float* mo = (const float*)d_in[0];  // model_output (4,2,256,256) f32
    const float* gt = (const float*)d_in[1];  // ground_truth (4,1,256,256) f32
    float* out = (float*)d_out;

    dim3 grid1(64, BB);
    k_rowpass<<<grid1, 256>>>(mo, gt, out);

    // colpass with programmatic dependent launch (overlaps rowpass execution)
    cudaLaunchConfig_t cfg = {};
    cfg.gridDim = dim3(8, 8, BB);
    cfg.blockDim = dim3(256, 1, 1);
    cudaLaunchAttribute attr[1];
    attr[0].id = cudaLaunchAttributeProgrammaticStreamSerialization;
    attr[0].val.programmaticStreamSerializationAllowed = 1;
    cfg.attrs = attr;
    cfg.numAttrs = 1;
    cudaError_t e = cudaLaunchKernelEx(&cfg, k_colpass, out);
    if (e != cudaSuccess) {  // fallback: plain ordered launch (still correct)
        dim3 grid2(8, 8, BB);
        k_colpass<<<grid2, 256>>>(out);
    }
}